// round 4
// baseline (speedup 1.0000x reference)
#include <cuda_runtime.h>
#include <cstdint>

#define IMG   4096
#define OUT   4097
#define TX    128
#define TY    32
#define XP    (TX + 5)   // 133  x-tile pitch (floats)
#define XR    (TY + 5)   // 37   x-tile rows
#define HP    (TX + 3)   // 131  hist-tile pitch (u64)
#define HR    (TY + 3)   // 35   hist-tile rows
#define OPLANE (OUT * OUT)
#define HTY   (TY / 2)   // 16 output rows per thread

#define XS_BYTES   ((XR * XP * 4 + 7) & ~7)
#define SMEM_BYTES (XS_BYTES + HR * HP * 8)     // ~55 KB

typedef unsigned long long u64;
typedef unsigned int       u32;

// predicated packed add: if (pm == P) acc += v  (two fp32 lanes at once)
#define PRED_ADD2(acc, pm, P, v)                                              \
    asm("{ .reg .pred p; setp.eq.u32 p, %1, %2; @p add.rn.f32x2 %0, %0, %3; }" \
        : "+l"(acc) : "r"(pm), "n"(P), "l"(v))

#define ADD2(d, a, b)                                                         \
    asm("add.rn.f32x2 %0, %1, %2;" : "=l"(d) : "l"(a), "l"(b))

#define FMA2(d, a, b, c)                                                      \
    asm("fma.rn.f32x2 %0, %1, %2, %3;" : "=l"(d) : "l"(a), "l"(b), "l"(c))

// route one hist row (4 packed pixels) into rs[4] (accumulating)
static __device__ __forceinline__ void accum_row(const u64* __restrict__ p, u64 rs[4]) {
#pragma unroll
    for (int j = 0; j < 4; ++j) {
        u64 h  = p[j];
        u32 pm = (u32)h & 3u;           // pair index in low 2 bits of lo lane
        PRED_ADD2(rs[0], pm, 0, h);
        PRED_ADD2(rs[1], pm, 1, h);
        PRED_ADD2(rs[2], pm, 2, h);
        PRED_ADD2(rs[3], pm, 3, h);
    }
}

__global__ __launch_bounds__(256)
void sift_fused4_kernel(const float* __restrict__ x, float* __restrict__ out)
{
    extern __shared__ char smem[];
    float* xs = (float*)smem;
    u64*   hs = (u64*)(smem + XS_BYTES);

    const int tid = threadIdx.x;
    const int ox0 = blockIdx.x * TX;
    const int oy0 = blockIdx.y * TY;

    // ---- phase 1: load x tile, zero-padded halo
    for (int e = tid; e < XR * XP; e += 256) {
        int r  = e / XP;
        int c  = e - r * XP;
        int gy = oy0 - 3 + r;
        int gx = ox0 - 3 + c;
        float v = 0.0f;
        if ((unsigned)gy < (unsigned)IMG && (unsigned)gx < (unsigned)IMG)
            v = x[gy * IMG + gx];
        xs[e] = v;
    }
    __syncthreads();

    // ---- phase 2: separable sobel, column-sliding -> octant -> packed pair
    {
        int col, ra, rb;
        if (tid < 131) { col = tid;        ra = 0;  rb = (col >= 125) ? HR : 18; }
        else           { col = tid - 131;  ra = 18; rb = HR; }

        const int  gx    = ox0 - 2 + col;
        const bool colok = (unsigned)gx < (unsigned)IMG;
        const float* xc  = xs + col;
        u64* hc          = hs + ra * HP + col;

        // warm-up: xs rows ra, ra+1
        float d0, d1, s0, s1;
        {
            const float* p = xc + ra * XP;
            float aL = p[0], aC = p[1], aR = p[2];
            d0 = aR - aL;  s0 = aL + 2.0f * aC + aR;
            p += XP;
            aL = p[0]; aC = p[1]; aR = p[2];
            d1 = aR - aL;  s1 = aL + 2.0f * aC + aR;
        }
        const float* p = xc + (ra + 2) * XP;
        int gy = oy0 - 2 + ra;
        for (int hy = ra; hy < rb; ++hy) {
            float aL = p[0], aC = p[1], aR = p[2];
            float d2 = aR - aL;
            float s2 = aL + 2.0f * aC + aR;
            float dx = d0 + 2.0f * d1 + d2;
            float dy = s2 - s0;

            float sq = dx * dx + dy * dy;
            float rs_;
            asm("rsqrt.approx.f32 %0, %1;" : "=f"(rs_) : "f"(sq));
            float mag = (sq > 0.0f) ? sq * rs_ : 0.0f;

            // octant of atan2(dy,dx): ties match strict-> first-occurrence argmax
            int   q3  = (dy < 0.0f) ? 4 : 0;
            float dx1 = q3 ? -dx : dx;
            float dy1 = q3 ? -dy : dy;
            int   q2  = (dx1 < 0.0f) ? 2 : 0;
            float dx2 = q2 ? dy1  : dx1;
            float dy2 = q2 ? -dx1 : dy1;
            int   q1  = (dy2 > dx2) ? 1 : 0;
            int   idx = q3 + q2 + q1;

            u32 magb = __float_as_uint(mag) & 0xFFFFFFFCu;
            u32 pm   = (u32)(idx >> 1);
            u32 lo, hi;
            if (idx & 1) { lo = pm;        hi = magb; }
            else         { lo = magb | pm; hi = 0u;   }
            u64 pv = ((u64)hi << 32) | lo;

            bool ok = colok && ((unsigned)gy < (unsigned)IMG);
            *hc = ok ? pv : 0ull;

            d0 = d1; d1 = d2; s0 = s1; s1 = s2;
            p  += XP;
            hc += HP;
            ++gy;
        }
    }
    __syncthreads();

    // ---- phase 3: 4x4 box sum, vertical sliding window, 4 packed-pair channels
    const int tx   = tid & (TX - 1);
    const int q    = tid >> 7;              // 0/1 -> tile half in y
    const int ox   = ox0 + tx;
    const int oy_s = oy0 + q * HTY;
    const bool oxok = (ox < OUT);
    const u64* hb = hs + tx;
    const int hy0 = q * HTY;

    const u64 NEG1 = 0xBF800000BF800000ull;  // {-1.0f, -1.0f}

    u64 row[4][4];
    u64 acc[4];
#pragma unroll
    for (int pp = 0; pp < 4; ++pp) acc[pp] = 0ull;
#pragma unroll
    for (int k = 0; k < 4; ++k) {
#pragma unroll
        for (int pp = 0; pp < 4; ++pp) row[k][pp] = 0ull;
        accum_row(hb + (hy0 + k) * HP, row[k]);
#pragma unroll
        for (int pp = 0; pp < 4; ++pp) ADD2(acc[pp], acc[pp], row[k][pp]);
    }

#pragma unroll 4
    for (int i = 0; i < HTY; ++i) {
        int oy = oy_s + i;
        if (oxok && oy < OUT) {
            int base = oy * OUT + ox;
#pragma unroll
            for (int pp = 0; pp < 4; ++pp) {
                u32 lo = (u32)acc[pp];
                u32 hi = (u32)(acc[pp] >> 32);
                out[(2 * pp)     * OPLANE + base] = __uint_as_float(lo);
                out[(2 * pp + 1) * OPLANE + base] = __uint_as_float(hi);
            }
        }
        if (i < HTY - 1) {
            const int k = i & 3;
#pragma unroll
            for (int pp = 0; pp < 4; ++pp)
                FMA2(acc[pp], row[k][pp], NEG1, acc[pp]);   // acc -= outgoing
#pragma unroll
            for (int pp = 0; pp < 4; ++pp) row[k][pp] = 0ull;
            accum_row(hb + (hy0 + 4 + i) * HP, row[k]);     // route incoming
#pragma unroll
            for (int pp = 0; pp < 4; ++pp)
                ADD2(acc[pp], acc[pp], row[k][pp]);         // acc += incoming
        }
    }
}

extern "C" void kernel_launch(void* const* d_in, const int* in_sizes, int n_in,
                              void* d_out, int out_size)
{
    (void)in_sizes; (void)n_in; (void)out_size;
    const float* x = (const float*)d_in[0];
    float* out = (float*)d_out;
    cudaFuncSetAttribute(sift_fused4_kernel,
                         cudaFuncAttributeMaxDynamicSharedMemorySize, SMEM_BYTES);
    dim3 grid((OUT + TX - 1) / TX, (OUT + TY - 1) / TY);  // 33 x 129
    sift_fused4_kernel<<<grid, 256, SMEM_BYTES>>>(x, out);
}

// round 5
// speedup vs baseline: 1.3383x; 1.3383x over previous
#include <cuda_runtime.h>
#include <cuda_bf16.h>
#include <cstdint>

#define IMG   4096
#define OUT   4097
#define TX    128
#define TY    32
#define XP    (TX + 5)   // 133  x-tile pitch (floats)
#define XR    (TY + 5)   // 37   x-tile rows
#define HP    (TX + 3)   // 131  hist-tile pitch (u64)
#define HR    (TY + 3)   // 35   hist-tile rows
#define OPLANE (OUT * OUT)
#define HTY   (TY / 2)

#define XS_BYTES  ((XR * XP * 4 + 7) & ~7)        // pad to 8B for u64 section
#define SMEM_BYTES (XS_BYTES + HR * HP * 8)       // ~56.4 KB

typedef unsigned long long u64;
typedef unsigned int       u32;

// predicated packed add: if (pm == P) acc += v  (two fp32 lanes at once)
#define PRED_ADD2(acc, pm, P, v)                                              \
    asm("{ .reg .pred p; setp.eq.u32 p, %1, %2; @p add.rn.f32x2 %0, %0, %3; }" \
        : "+l"(acc) : "r"(pm), "n"(P), "l"(v))

#define ADD2(d, a, b)                                                         \
    asm("add.rn.f32x2 %0, %1, %2;" : "=l"(d) : "l"(a), "l"(b))

#define FMA2(d, a, b, c)                                                      \
    asm("fma.rn.f32x2 %0, %1, %2, %3;" : "=l"(d) : "l"(a), "l"(b), "l"(c))

// route one hist row (4 packed pixels) into rs[4] (accumulating)
static __device__ __forceinline__ void accum_row(const u64* __restrict__ p, u64 rs[4]) {
#pragma unroll
    for (int j = 0; j < 4; ++j) {
        u64 h  = p[j];
        u32 pm = (u32)h & 3u;           // pair index in low 2 bits of lo lane
        PRED_ADD2(rs[0], pm, 0, h);
        PRED_ADD2(rs[1], pm, 1, h);
        PRED_ADD2(rs[2], pm, 2, h);
        PRED_ADD2(rs[3], pm, 3, h);
    }
}

__global__ __launch_bounds__(256)
void sift_fused5_kernel(const float* __restrict__ x, float* __restrict__ out)
{
    extern __shared__ char smem[];
    float* xs = (float*)smem;
    u64*   hs = (u64*)(smem + XS_BYTES);

    const int tid = threadIdx.x;
    const int ox0 = blockIdx.x * TX;
    const int oy0 = blockIdx.y * TY;

    // ---- phase 1: load x tile, zero-padded halo
    for (int e = tid; e < XR * XP; e += 256) {
        int r  = e / XP;
        int c  = e - r * XP;
        int gy = oy0 - 3 + r;
        int gx = ox0 - 3 + c;
        float v = 0.0f;
        if ((unsigned)gy < (unsigned)IMG && (unsigned)gx < (unsigned)IMG)
            v = x[gy * IMG + gx];
        xs[e] = v;
    }
    __syncthreads();

    // ---- phase 2: sobel -> octant (bit tricks) -> pre-routed packed pair
    for (int e = tid; e < HR * HP; e += 256) {
        int hy = e / HP;
        int hx = e - hy * HP;
        int gy = oy0 - 2 + hy;
        int gx = ox0 - 2 + hx;
        u64 pv = 0ull;
        if ((unsigned)gy < (unsigned)IMG && (unsigned)gx < (unsigned)IMG) {
            const float* p = xs + hy * XP + hx;   // top-left of 3x3
            float a00 = p[0],      a01 = p[1],          a02 = p[2];
            float a10 = p[XP],     a12 = p[XP + 2];
            float a20 = p[2 * XP], a21 = p[2 * XP + 1], a22 = p[2 * XP + 2];
            // column sums: S_j = r0 + 2 r1 + r2 (for dx), D_j = r2 - r0 (for dy)
            float S0 = a00 + 2.0f * a10 + a20;
            float S2 = a02 + 2.0f * a12 + a22;
            float D0 = a20 - a00;
            float D1 = a21 - a01;
            float D2 = a22 - a02;
            float dx = S2 - S0;
            float dy = D0 + 2.0f * D1 + D2;

            float sq = dx * dx + dy * dy;
            float rs_;
            asm("rsqrt.approx.f32 %0, %1;" : "=f"(rs_) : "f"(sq));
            float mag = (sq >= 1.17549435e-38f) ? sq * rs_ : 0.0f;

            // octant of atan2(dy,dx) via sign bits + |dy|>|dx|
            u32 bx = __float_as_uint(dx);
            u32 by = __float_as_uint(dy);
            u32 b2 = by >> 31;
            u32 b1 = (bx ^ by) >> 31;
            u32 c  = (fabsf(dy) > fabsf(dx)) ? 1u : 0u;
            u32 b0 = c ^ b1;
            u32 idx = (b2 << 2) | (b1 << 1) | b0;

            u32 magb = __float_as_uint(mag) & 0xFFFFFFFCu;
            u32 pm   = idx >> 1;
            u32 lo, hi;
            if (idx & 1) { lo = pm;        hi = magb; }
            else         { lo = magb | pm; hi = 0u;   }
            pv = ((u64)hi << 32) | lo;
        }
        hs[e] = pv;
    }
    __syncthreads();

    // ---- phase 3: 4x4 box sum, vertical sliding window, 4 packed-pair channels
    const int tx   = tid & (TX - 1);
    const int q    = tid >> 7;              // 0/1 -> tile half in y
    const int ox   = ox0 + tx;
    const int oy_s = oy0 + q * HTY;
    const bool oxok = (ox < OUT);
    const u64* hb = hs + tx;
    const int hy0 = q * HTY;

    const u64 NEG1 = 0xBF800000BF800000ull;  // {-1.0f, -1.0f}

    u64 row[4][4];
    u64 acc[4];
#pragma unroll
    for (int pp = 0; pp < 4; ++pp) acc[pp] = 0ull;
#pragma unroll
    for (int k = 0; k < 4; ++k) {
#pragma unroll
        for (int pp = 0; pp < 4; ++pp) row[k][pp] = 0ull;
        accum_row(hb + (hy0 + k) * HP, row[k]);
#pragma unroll
        for (int pp = 0; pp < 4; ++pp) ADD2(acc[pp], acc[pp], row[k][pp]);
    }

#pragma unroll 4
    for (int i = 0; i < HTY; ++i) {
        int oy = oy_s + i;
        if (oxok && oy < OUT) {
            int base = oy * OUT + ox;
#pragma unroll
            for (int pp = 0; pp < 4; ++pp) {
                u32 lo = (u32)acc[pp];
                u32 hi = (u32)(acc[pp] >> 32);
                out[(2 * pp)     * OPLANE + base] = __uint_as_float(lo);
                out[(2 * pp + 1) * OPLANE + base] = __uint_as_float(hi);
            }
        }
        if (i < HTY - 1) {
            u64 nr[4];
#pragma unroll
            for (int pp = 0; pp < 4; ++pp) nr[pp] = 0ull;
            accum_row(hb + (hy0 + 4 + i) * HP, nr);
            const int k = i & 3;
#pragma unroll
            for (int pp = 0; pp < 4; ++pp) {
                u64 t;
                ADD2(t, acc[pp], nr[pp]);            // acc + new
                FMA2(acc[pp], row[k][pp], NEG1, t);  // - old
                row[k][pp] = nr[pp];
            }
        }
    }
}

extern "C" void kernel_launch(void* const* d_in, const int* in_sizes, int n_in,
                              void* d_out, int out_size)
{
    (void)in_sizes; (void)n_in; (void)out_size;
    const float* x = (const float*)d_in[0];
    float* out = (float*)d_out;
    cudaFuncSetAttribute(sift_fused5_kernel,
                         cudaFuncAttributeMaxDynamicSharedMemorySize, SMEM_BYTES);
    dim3 grid((OUT + TX - 1) / TX, (OUT + TY - 1) / TY);  // 33 x 129
    sift_fused5_kernel<<<grid, 256, SMEM_BYTES>>>(x, out);
}

// round 7
// speedup vs baseline: 1.5132x; 1.1307x over previous
#include <cuda_runtime.h>
#include <cuda_bf16.h>
#include <cstdint>

#define IMG   4096
#define OUT   4097
#define TX    128
#define TY    32
#define XP2   136        // x-tile pitch (floats), padded for float4
#define XR    37         // x-tile rows
#define HP    (TX + 3)   // 131  hist-tile pitch (u64)
#define HR    (TY + 3)   // 35   hist-tile rows
#define OPLANE (OUT * OUT)
#define HTY   (TY / 2)

#define XS_BYTES  (XR * XP2 * 4)                  // 20128, 8B-aligned
#define SMEM_BYTES (XS_BYTES + HR * HP * 8)       // ~55.5 KB

typedef unsigned long long u64;
typedef unsigned int       u32;

// predicated packed add: if (pm == P) acc += v  (two fp32 lanes at once)
#define PRED_ADD2(acc, pm, P, v)                                              \
    asm("{ .reg .pred p; setp.eq.u32 p, %1, %2; @p add.rn.f32x2 %0, %0, %3; }" \
        : "+l"(acc) : "r"(pm), "n"(P), "l"(v))

#define ADD2(d, a, b)                                                         \
    asm("add.rn.f32x2 %0, %1, %2;" : "=l"(d) : "l"(a), "l"(b))

#define FMA2(d, a, b, c)                                                      \
    asm("fma.rn.f32x2 %0, %1, %2, %3;" : "=l"(d) : "l"(a), "l"(b), "l"(c))

// route one hist row (4 packed pixels) into rs[4] (accumulating)
static __device__ __forceinline__ void accum_row(const u64* __restrict__ p, u64 rs[4]) {
#pragma unroll
    for (int j = 0; j < 4; ++j) {
        u64 h  = p[j];
        u32 pm = (u32)h & 3u;           // pair index in low 2 bits of lo lane
        PRED_ADD2(rs[0], pm, 0, h);
        PRED_ADD2(rs[1], pm, 1, h);
        PRED_ADD2(rs[2], pm, 2, h);
        PRED_ADD2(rs[3], pm, 3, h);
    }
}

// sobel + octant + pack for one hist element; p = top-left of 3x3 in xs
static __device__ __forceinline__ u64 hist_val(const float* __restrict__ p) {
    float a00 = p[0],       a01 = p[1],           a02 = p[2];
    float a10 = p[XP2],     a12 = p[XP2 + 2];
    float a20 = p[2 * XP2], a21 = p[2 * XP2 + 1], a22 = p[2 * XP2 + 2];
    float S0 = a00 + 2.0f * a10 + a20;
    float S2 = a02 + 2.0f * a12 + a22;
    float D0 = a20 - a00;
    float D1 = a21 - a01;
    float D2 = a22 - a02;
    float dx = S2 - S0;
    float dy = D0 + 2.0f * D1 + D2;

    float sq = dx * dx + dy * dy;
    float sg = fmaxf(sq, 1.17549435e-38f);
    float rs_;
    asm("rsqrt.approx.f32 %0, %1;" : "=f"(rs_) : "f"(sg));
    float mag = sq * rs_;

    // octant of atan2(dy,dx) via sign bits + |dy|>|dx|; tie rules match
    // strict-> first-occurrence argmax of the 8 cosine projections.
    u32 bx = __float_as_uint(dx);
    u32 by = __float_as_uint(dy);
    u32 b2 = by >> 31;
    u32 b1 = (bx ^ by) >> 31;
    u32 c  = (fabsf(dy) > fabsf(dx)) ? 1u : 0u;
    u32 b0 = c ^ b1;
    u32 idx = (b2 << 2) | (b1 << 1) | b0;

    u32 magb = __float_as_uint(mag) & 0xFFFFFFFCu;
    u32 pm   = idx >> 1;
    u32 lo, hi;
    if (idx & 1) { lo = pm;        hi = magb; }
    else         { lo = magb | pm; hi = 0u;   }
    return ((u64)hi << 32) | lo;
}

__global__ __launch_bounds__(256)
void sift_fused7_kernel(const float* __restrict__ x, float* __restrict__ out)
{
    extern __shared__ char smem[];
    float* xs = (float*)smem;
    u64*   hs = (u64*)(smem + XS_BYTES);

    const int tid = threadIdx.x;
    const int ox0 = blockIdx.x * TX;
    const int oy0 = blockIdx.y * TY;

    // ---- phase 1: load x tile (cols gx = ox0-4+c, rows gy = oy0-3+r), zero-padded
    const bool ld_interior = (ox0 >= 4) && (ox0 <= IMG - 132) &&
                             (oy0 >= 3) && (oy0 <= IMG - 34);
    if (ld_interior) {
        const float* xb = x + (oy0 - 3) * IMG + (ox0 - 4);   // 16B-aligned
#pragma unroll 5
        for (int e = tid; e < XR * 34; e += 256) {
            int r  = e / 34;
            int c4 = e - r * 34;
            float4 v = *(const float4*)(xb + r * IMG + 4 * c4);
            *(float4*)&xs[r * XP2 + 4 * c4] = v;
        }
    } else {
        for (int e = tid; e < XR * XP2; e += 256) {
            int r  = e / XP2;
            int c  = e - r * XP2;
            int gy = oy0 - 3 + r;
            int gx = ox0 - 4 + c;
            float v = 0.0f;
            if ((unsigned)gy < (unsigned)IMG && (unsigned)gx < (unsigned)IMG)
                v = x[gy * IMG + gx];
            xs[r * XP2 + c] = v;
        }
    }
    __syncthreads();

    // ---- phase 2: sobel -> octant -> pre-routed packed pair.
    // Hist tile spans gx in [ox0-2, ox0+130], gy in [oy0-2, oy0+32].
    // Interior CTAs (hist tile fully inside the image) skip the OOB guard.
    const bool h_interior = (ox0 >= 2) && (ox0 + TX + 2 < IMG) &&
                            (oy0 >= 2) && (oy0 + TY + 2 < IMG);
    if (h_interior) {
        for (int e = tid; e < HR * HP; e += 256) {
            int hy = e / HP;
            int hx = e - hy * HP;
            hs[e] = hist_val(xs + hy * XP2 + hx + 1);
        }
    } else {
        for (int e = tid; e < HR * HP; e += 256) {
            int hy = e / HP;
            int hx = e - hy * HP;
            int gy = oy0 - 2 + hy;
            int gx = ox0 - 2 + hx;
            u64 pv = 0ull;
            if ((unsigned)gy < (unsigned)IMG && (unsigned)gx < (unsigned)IMG)
                pv = hist_val(xs + hy * XP2 + hx + 1);
            hs[e] = pv;
        }
    }
    __syncthreads();

    // ---- phase 3: 4x4 box sum, vertical sliding window, 4 packed-pair channels
    const int tx   = tid & (TX - 1);
    const int q    = tid >> 7;              // 0/1 -> tile half in y
    const int ox   = ox0 + tx;
    const int oy_s = oy0 + q * HTY;
    const bool oxok = (ox < OUT);
    const u64* hb = hs + tx;
    const int hy0 = q * HTY;

    const u64 NEG1 = 0xBF800000BF800000ull;  // {-1.0f, -1.0f}

    u64 row[4][4];
    u64 acc[4];
#pragma unroll
    for (int pp = 0; pp < 4; ++pp) acc[pp] = 0ull;
#pragma unroll
    for (int k = 0; k < 4; ++k) {
#pragma unroll
        for (int pp = 0; pp < 4; ++pp) row[k][pp] = 0ull;
        accum_row(hb + (hy0 + k) * HP, row[k]);
#pragma unroll
        for (int pp = 0; pp < 4; ++pp) ADD2(acc[pp], acc[pp], row[k][pp]);
    }

#pragma unroll 4
    for (int i = 0; i < HTY; ++i) {
        int oy = oy_s + i;
        if (oxok && oy < OUT) {
            int base = oy * OUT + ox;
#pragma unroll
            for (int pp = 0; pp < 4; ++pp) {
                u32 lo = (u32)acc[pp];
                u32 hi = (u32)(acc[pp] >> 32);
                out[(2 * pp)     * OPLANE + base] = __uint_as_float(lo);
                out[(2 * pp + 1) * OPLANE + base] = __uint_as_float(hi);
            }
        }
        if (i < HTY - 1) {
            u64 nr[4];
#pragma unroll
            for (int pp = 0; pp < 4; ++pp) nr[pp] = 0ull;
            accum_row(hb + (hy0 + 4 + i) * HP, nr);
            const int k = i & 3;
#pragma unroll
            for (int pp = 0; pp < 4; ++pp) {
                u64 t;
                ADD2(t, acc[pp], nr[pp]);            // acc + new
                FMA2(acc[pp], row[k][pp], NEG1, t);  // - old
                row[k][pp] = nr[pp];
            }
        }
    }
}

extern "C" void kernel_launch(void* const* d_in, const int* in_sizes, int n_in,
                              void* d_out, int out_size)
{
    (void)in_sizes; (void)n_in; (void)out_size;
    const float* x = (const float*)d_in[0];
    float* out = (float*)d_out;
    cudaFuncSetAttribute(sift_fused7_kernel,
                         cudaFuncAttributeMaxDynamicSharedMemorySize, SMEM_BYTES);
    dim3 grid((OUT + TX - 1) / TX, (OUT + TY - 1) / TY);  // 33 x 129
    sift_fused7_kernel<<<grid, 256, SMEM_BYTES>>>(x, out);
}